// round 1
// baseline (speedup 1.0000x reference)
#include <cuda_runtime.h>

#define BATCH 2
#define SEQ   2048
#define EMB   768
#define NHEAD 12
#define HDIM  64
#define MTOT  (BATCH*SEQ)   // 4096
#define QKVN  (3*EMB)       // 2304

// Scratch (allocation-free): Q/K/V in [B,H,N,D], attention out in [B,N,C]
__device__ float g_Q[BATCH*NHEAD*SEQ*HDIM];
__device__ float g_K[BATCH*NHEAD*SEQ*HDIM];
__device__ float g_V[BATCH*NHEAD*SEQ*HDIM];
__device__ float g_AO[MTOT*EMB];

// ----------------------------------------------------------------------------
// GEMM: out[M, Ncols] = A[M,K] @ W[Ncols,K]^T + bias
// 128x128 block tile, BK=8, 256 threads, 8x8 per thread.
// QKV_SCATTER: scatter columns into g_Q/g_K/g_V ([B,H,N,D]); else write `out`.
// ----------------------------------------------------------------------------
template<bool QKV_SCATTER>
__global__ __launch_bounds__(256) void gemm_kernel(
    const float* __restrict__ A, const float* __restrict__ W,
    const float* __restrict__ bias, float* __restrict__ out, int K)
{
    __shared__ float As[8][128];
    __shared__ float Bs[8][128];

    const float* Ap = QKV_SCATTER ? A : (const float*)g_AO;

    const int row0 = blockIdx.y * 128;
    const int col0 = blockIdx.x * 128;
    const int tid  = threadIdx.x;
    const int lr = tid >> 1;            // 0..127 (tile row/col for loads)
    const int lk = (tid & 1) * 4;       // 0 or 4 (k offset for loads)
    const int tr = (tid >> 4) * 8;      // thread tile row offset
    const int tc = (tid & 15) * 8;      // thread tile col offset

    float acc[8][8];
    #pragma unroll
    for (int i = 0; i < 8; i++)
        #pragma unroll
        for (int j = 0; j < 8; j++) acc[i][j] = 0.f;

    for (int k0 = 0; k0 < K; k0 += 8) {
        float4 av = *(const float4*)(Ap + (size_t)(row0 + lr) * K + k0 + lk);
        float4 bv = *(const float4*)(W  + (size_t)(col0 + lr) * K + k0 + lk);
        As[lk+0][lr] = av.x; As[lk+1][lr] = av.y; As[lk+2][lr] = av.z; As[lk+3][lr] = av.w;
        Bs[lk+0][lr] = bv.x; Bs[lk+1][lr] = bv.y; Bs[lk+2][lr] = bv.z; Bs[lk+3][lr] = bv.w;
        __syncthreads();

        #pragma unroll
        for (int kk = 0; kk < 8; kk++) {
            float a[8], b[8];
            *(float4*)&a[0] = *(const float4*)&As[kk][tr];
            *(float4*)&a[4] = *(const float4*)&As[kk][tr + 4];
            *(float4*)&b[0] = *(const float4*)&Bs[kk][tc];
            *(float4*)&b[4] = *(const float4*)&Bs[kk][tc + 4];
            #pragma unroll
            for (int i = 0; i < 8; i++)
                #pragma unroll
                for (int j = 0; j < 8; j++)
                    acc[i][j] += a[i] * b[j];
        }
        __syncthreads();
    }

    #pragma unroll
    for (int i = 0; i < 8; i++) {
        int row   = row0 + tr + i;
        int b_idx = row >> 11;       // / SEQ
        int n_idx = row & (SEQ - 1);
        #pragma unroll
        for (int j = 0; j < 8; j++) {
            int col = col0 + tc + j;
            float v = acc[i][j] + bias[col];
            if (QKV_SCATTER) {
                int part = col / EMB;              // 0=Q 1=K 2=V
                int cc   = col - part * EMB;
                int h    = cc >> 6;
                int d    = cc & 63;
                float* dst = (part == 0) ? g_Q : (part == 1 ? g_K : g_V);
                dst[(((size_t)(b_idx * NHEAD + h)) * SEQ + n_idx) * HDIM + d] = v;
            } else {
                out[(size_t)row * EMB + col] = v;
            }
        }
    }
}

// ----------------------------------------------------------------------------
// Flash attention: one thread = one query row (q,o in registers).
// Block = 128 query rows; iterate 64-key K/V tiles in smem; online softmax
// processed in 16-key chunks. Writes g_AO in [B,N,C] layout.
// ----------------------------------------------------------------------------
__global__ __launch_bounds__(128) void flash_kernel()
{
    __shared__ float Ks[64 * 64];
    __shared__ float Vs[64 * 64];

    const int tid = threadIdx.x;
    const int bh  = blockIdx.y;
    const int r   = blockIdx.x * 128 + tid;     // query index within sequence
    const size_t base = (size_t)bh * SEQ * HDIM;

    float q[64], o[64];
    #pragma unroll
    for (int i = 0; i < 16; i++) {
        float4 v = *(const float4*)(g_Q + base + (size_t)r * HDIM + i * 4);
        q[i*4+0] = v.x; q[i*4+1] = v.y; q[i*4+2] = v.z; q[i*4+3] = v.w;
    }
    #pragma unroll
    for (int d = 0; d < 64; d++) o[d] = 0.f;

    float m = -1e30f, l = 0.f;
    const float scale = 0.125f;   // 1/sqrt(64)

    for (int kt = 0; kt < SEQ; kt += 64) {
        const float4* kg = (const float4*)(g_K + base + (size_t)kt * HDIM);
        const float4* vg = (const float4*)(g_V + base + (size_t)kt * HDIM);
        #pragma unroll
        for (int i = 0; i < 8; i++) {
            ((float4*)Ks)[tid + i * 128] = kg[tid + i * 128];
            ((float4*)Vs)[tid + i * 128] = vg[tid + i * 128];
        }
        __syncthreads();

        #pragma unroll 1
        for (int c = 0; c < 4; c++) {
            float s[16];
            #pragma unroll
            for (int j = 0; j < 16; j++) {
                const float* kr = Ks + (c * 16 + j) * 64;
                float a = 0.f;
                #pragma unroll
                for (int d4 = 0; d4 < 16; d4++) {
                    float4 kv = *(const float4*)(kr + d4 * 4);
                    a += q[d4*4+0]*kv.x + q[d4*4+1]*kv.y
                       + q[d4*4+2]*kv.z + q[d4*4+3]*kv.w;
                }
                s[j] = a * scale;
            }
            float mc = s[0];
            #pragma unroll
            for (int j = 1; j < 16; j++) mc = fmaxf(mc, s[j]);
            float mn = fmaxf(m, mc);
            float corr = __expf(m - mn);
            l *= corr;
            #pragma unroll
            for (int d = 0; d < 64; d++) o[d] *= corr;
            #pragma unroll
            for (int j = 0; j < 16; j++) {
                float p = __expf(s[j] - mn);
                l += p;
                const float* vr = Vs + (c * 16 + j) * 64;
                #pragma unroll
                for (int d4 = 0; d4 < 16; d4++) {
                    float4 vv = *(const float4*)(vr + d4 * 4);
                    o[d4*4+0] += p * vv.x; o[d4*4+1] += p * vv.y;
                    o[d4*4+2] += p * vv.z; o[d4*4+3] += p * vv.w;
                }
            }
            m = mn;
        }
        __syncthreads();
    }

    float inv = 1.f / l;
    int b_idx = bh / NHEAD, h = bh % NHEAD;
    float* op = g_AO + ((size_t)(b_idx * SEQ + r)) * EMB + h * HDIM;
    #pragma unroll
    for (int d4 = 0; d4 < 16; d4++) {
        float4 v;
        v.x = o[d4*4+0] * inv; v.y = o[d4*4+1] * inv;
        v.z = o[d4*4+2] * inv; v.w = o[d4*4+3] * inv;
        *(float4*)(op + d4 * 4) = v;
    }
}

// ----------------------------------------------------------------------------
extern "C" void kernel_launch(void* const* d_in, const int* in_sizes, int n_in,
                              void* d_out, int out_size)
{
    const float* x      = (const float*)d_in[0];
    const float* w_qkv  = (const float*)d_in[1];
    const float* b_qkv  = (const float*)d_in[2];
    const float* w_proj = (const float*)d_in[3];
    const float* b_proj = (const float*)d_in[4];
    float* out = (float*)d_out;

    // 1) QKV GEMM + bias + scatter to Q/K/V [B,H,N,D]
    dim3 g1(QKVN / 128, MTOT / 128);   // 18 x 32
    gemm_kernel<true><<<g1, 256>>>(x, w_qkv, b_qkv, nullptr, EMB);

    // 2) Flash attention -> g_AO [B,N,C]
    dim3 g2(SEQ / 128, BATCH * NHEAD); // 16 x 24
    flash_kernel<<<g2, 128>>>();

    // 3) Projection GEMM + bias -> out
    dim3 g3(EMB / 128, MTOT / 128);    // 6 x 32
    gemm_kernel<false><<<g3, 256>>>(nullptr, w_proj, b_proj, out, EMB);
}

// round 3
// speedup vs baseline: 3.1335x; 3.1335x over previous
#include <cuda_runtime.h>
#include <cstdint>

#define SEQ   2048
#define EMB   768
#define NHEAD 12
#define HDIM  64
#define BH    24          // batch * heads
#define MTOT  4096        // batch * seq

// ---------------- scratch (allocation-free) ----------------
__device__ float g_Qs[(size_t)BH*SEQ*HDIM];   // scaled Q  [bh, n, d]
__device__ float g_Kc[(size_t)BH*SEQ*HDIM];   // K         [bh, n, d]
__device__ float g_Vt[(size_t)BH*HDIM*SEQ];   // V^T       [bh, d, n]
__device__ float g_S [(size_t)BH*SEQ*SEQ];    // scores -> probs (in place)
__device__ float g_AO[(size_t)MTOT*EMB];      // attention out [b, n, c]

// ---------------- helpers ----------------
__device__ __forceinline__ uint32_t f2tf(float x){
    uint32_t r; asm("cvt.rna.tf32.f32 %0, %1;" : "=r"(r) : "f"(x)); return r;
}
__device__ __forceinline__ void cp16(uint32_t dst, const void* src){
    asm volatile("cp.async.cg.shared.global [%0], [%1], 16;" :: "r"(dst), "l"(src));
}
__device__ __forceinline__ void cp_commit(){
    asm volatile("cp.async.commit_group;" ::: "memory");
}
template<int N>
__device__ __forceinline__ void cp_wait(){
    asm volatile("cp.async.wait_group %0;" :: "n"(N) : "memory");
}
__device__ __forceinline__ void mma_tf32(float* c, const uint32_t* a, const uint32_t* b){
    asm volatile(
        "mma.sync.aligned.m16n8k8.row.col.f32.tf32.tf32.f32 "
        "{%0,%1,%2,%3}, {%4,%5,%6,%7}, {%8,%9}, {%0,%1,%2,%3};"
        : "+f"(c[0]), "+f"(c[1]), "+f"(c[2]), "+f"(c[3])
        : "r"(a[0]), "r"(a[1]), "r"(a[2]), "r"(a[3]), "r"(b[0]), "r"(b[1]));
}

// ----------------------------------------------------------------------------
// tf32 mma.sync GEMM: D[128, BN] tile = A[M,K] @ B[N,K]^T (+bias), MODE epilogue
//   MODE 0: QKV    (A=x,  B=w_qkv)  -> scatter to g_Qs (x0.125) / g_Kc / g_Vt
//   MODE 1: S=QK^T (batched bh)     -> g_S
//   MODE 2: O=PV   (batched bh, BN=64, B=g_Vt) -> g_AO
//   MODE 3: proj   (A=g_AO, B=w_proj) -> Cout + bias
// 256 threads = 8 warps (4 M x 2 N). BK=16. smem stride 20 (conflict-free).
// ----------------------------------------------------------------------------
template<int BN, int MODE>
__global__ void __launch_bounds__(256) mm_kernel(
    const float* __restrict__ Ain, const float* __restrict__ Bin,
    const float* __restrict__ bias, float* __restrict__ Cout)
{
    constexpr int BK   = 16;
    constexpr int LDS  = 20;                 // padded floats per row
    constexpr int NT   = BN / 16;            // n8 tiles per warp (warpN = BN/2)

    __shared__ float As[2][128 * LDS];
    __shared__ float Bs[2][BN  * LDS];

    const int tid  = threadIdx.x;
    const int wid  = tid >> 5, lane = tid & 31;
    const int lq   = lane >> 2, lr = lane & 3;
    const int mOff = (wid & 3) * 32;
    const int nOff = (wid >> 2) * (BN / 2);
    const int z    = blockIdx.z;
    const int row0 = blockIdx.y * 128, col0 = blockIdx.x * BN;

    const float* Ap; const float* Bp; int lda, ldb, K;
    if (MODE == 0)      { Ap = Ain;                           lda = EMB;  Bp = Bin;                           ldb = EMB;  K = EMB; }
    else if (MODE == 1) { Ap = g_Qs + (size_t)z * SEQ * HDIM; lda = HDIM; Bp = g_Kc + (size_t)z * SEQ * HDIM; ldb = HDIM; K = HDIM; }
    else if (MODE == 2) { Ap = g_S  + (size_t)z * SEQ * SEQ;  lda = SEQ;  Bp = g_Vt + (size_t)z * HDIM * SEQ; ldb = SEQ;  K = SEQ; }
    else                { Ap = g_AO;                          lda = EMB;  Bp = Bin;                           ldb = EMB;  K = EMB; }

    const uint32_t sA = (uint32_t)__cvta_generic_to_shared(&As[0][0]);
    const uint32_t sB = (uint32_t)__cvta_generic_to_shared(&Bs[0][0]);
    constexpr uint32_t ABYT = 128 * LDS * 4;
    constexpr uint32_t BBYT = BN  * LDS * 4;

    auto load_tile = [&](int kt, int buf){
        const float* ag = Ap + (size_t)row0 * lda + kt * BK;
        const uint32_t da = sA + buf * ABYT;
        #pragma unroll
        for (int i = 0; i < 2; i++){                     // 512 chunks / 256 thr
            int ch = tid + i * 256, r = ch >> 2, c4 = ch & 3;
            cp16(da + (uint32_t)(r * LDS + c4 * 4) * 4,
                 ag + (size_t)r * lda + c4 * 4);
        }
        const float* bg = Bp + (size_t)col0 * ldb + kt * BK;
        const uint32_t db = sB + buf * BBYT;
        #pragma unroll
        for (int i = 0; i < BN / 64; i++){
            int ch = tid + i * 256, r = ch >> 2, c4 = ch & 3;
            cp16(db + (uint32_t)(r * LDS + c4 * 4) * 4,
                 bg + (size_t)r * ldb + c4 * 4);
        }
    };

    float acc[2][NT][4];
    #pragma unroll
    for (int mt = 0; mt < 2; mt++)
        #pragma unroll
        for (int nt = 0; nt < NT; nt++)
            #pragma unroll
            for (int j = 0; j < 4; j++) acc[mt][nt][j] = 0.f;

    load_tile(0, 0);
    cp_commit();

    const int KT = K / BK;
    for (int kt = 0; kt < KT; kt++){
        if (kt + 1 < KT){ load_tile(kt + 1, (kt + 1) & 1); cp_commit(); cp_wait<1>(); }
        else            { cp_wait<0>(); }
        __syncthreads();

        const float* a_s = As[kt & 1];
        const float* b_s = Bs[kt & 1];
        #pragma unroll
        for (int s = 0; s < 2; s++){
            const int k0 = s * 8;
            uint32_t af[2][4];
            #pragma unroll
            for (int mt = 0; mt < 2; mt++){
                const int r = mOff + mt * 16 + lq;
                af[mt][0] = f2tf(a_s[(r    ) * LDS + k0 + lr    ]);
                af[mt][1] = f2tf(a_s[(r + 8) * LDS + k0 + lr    ]);
                af[mt][2] = f2tf(a_s[(r    ) * LDS + k0 + lr + 4]);
                af[mt][3] = f2tf(a_s[(r + 8) * LDS + k0 + lr + 4]);
            }
            uint32_t bf[NT][2];
            #pragma unroll
            for (int nt = 0; nt < NT; nt++){
                const int c = nOff + nt * 8 + lq;
                bf[nt][0] = f2tf(b_s[c * LDS + k0 + lr    ]);
                bf[nt][1] = f2tf(b_s[c * LDS + k0 + lr + 4]);
            }
            #pragma unroll
            for (int mt = 0; mt < 2; mt++)
                #pragma unroll
                for (int nt = 0; nt < NT; nt++)
                    mma_tf32(acc[mt][nt], af[mt], bf[nt]);
        }
        __syncthreads();
    }

    // ---------------- epilogue ----------------
    auto emit = [&](int r, int col, float v0, float v1){
        if (MODE == 0){
            const int part = col / EMB, cc = col - part * EMB;
            const int h = cc >> 6, d = cc & 63;
            const int bidx = r >> 11, n = r & (SEQ - 1);
            const float bb0 = bias[col], bb1 = bias[col + 1];
            if (part < 2){
                float* dst = (part == 0 ? g_Qs : g_Kc)
                           + (((size_t)(bidx * NHEAD + h) * SEQ + n) * HDIM + d);
                const float sc = (part == 0) ? 0.125f : 1.0f;
                *(float2*)dst = make_float2((v0 + bb0) * sc, (v1 + bb1) * sc);
            } else {
                const size_t vb = ((size_t)(bidx * NHEAD + h) * HDIM + d) * SEQ + n;
                g_Vt[vb]       = v0 + bb0;
                g_Vt[vb + SEQ] = v1 + bb1;
            }
        } else if (MODE == 1){
            *(float2*)(g_S + (size_t)z * SEQ * SEQ + (size_t)r * SEQ + col)
                = make_float2(v0, v1);
        } else if (MODE == 2){
            const int bidx = z / NHEAD, h = z - bidx * NHEAD;
            *(float2*)(g_AO + ((size_t)(bidx * SEQ + r)) * EMB + h * HDIM + col)
                = make_float2(v0, v1);
        } else {
            *(float2*)(Cout + (size_t)r * EMB + col)
                = make_float2(v0 + bias[col], v1 + bias[col + 1]);
        }
    };

    #pragma unroll
    for (int mt = 0; mt < 2; mt++){
        const int r1 = row0 + mOff + mt * 16 + lq;
        #pragma unroll
        for (int nt = 0; nt < NT; nt++){
            const int col = col0 + nOff + nt * 8 + lr * 2;
            emit(r1,     col, acc[mt][nt][0], acc[mt][nt][1]);
            emit(r1 + 8, col, acc[mt][nt][2], acc[mt][nt][3]);
        }
    }
}

// ----------------------------------------------------------------------------
// Row softmax over g_S in place. One block per row (2048 floats).
// ----------------------------------------------------------------------------
__global__ void __launch_bounds__(256) softmax_kernel()
{
    __shared__ float red_max[8];
    __shared__ float red_sum[8];
    const size_t row = blockIdx.x;
    float* p = g_S + row * (size_t)SEQ;
    const int tid = threadIdx.x;

    float4 a = ((float4*)p)[tid];
    float4 b = ((float4*)p)[tid + 256];
    float mx = fmaxf(fmaxf(fmaxf(a.x, a.y), fmaxf(a.z, a.w)),
                     fmaxf(fmaxf(b.x, b.y), fmaxf(b.z, b.w)));
    #pragma unroll
    for (int o = 16; o; o >>= 1) mx = fmaxf(mx, __shfl_xor_sync(~0u, mx, o));
    if ((tid & 31) == 0) red_max[tid >> 5] = mx;
    __syncthreads();
    float m = red_max[0];
    #pragma unroll
    for (int i = 1; i < 8; i++) m = fmaxf(m, red_max[i]);

    a.x = __expf(a.x - m); a.y = __expf(a.y - m);
    a.z = __expf(a.z - m); a.w = __expf(a.w - m);
    b.x = __expf(b.x - m); b.y = __expf(b.y - m);
    b.z = __expf(b.z - m); b.w = __expf(b.w - m);
    float s = (a.x + a.y) + (a.z + a.w) + (b.x + b.y) + (b.z + b.w);
    #pragma unroll
    for (int o = 16; o; o >>= 1) s += __shfl_xor_sync(~0u, s, o);
    if ((tid & 31) == 0) red_sum[tid >> 5] = s;
    __syncthreads();
    float t = 0.f;
    #pragma unroll
    for (int i = 0; i < 8; i++) t += red_sum[i];
    const float inv = 1.0f / t;

    a.x *= inv; a.y *= inv; a.z *= inv; a.w *= inv;
    b.x *= inv; b.y *= inv; b.z *= inv; b.w *= inv;
    ((float4*)p)[tid] = a;
    ((float4*)p)[tid + 256] = b;
}

// ----------------------------------------------------------------------------
extern "C" void kernel_launch(void* const* d_in, const int* in_sizes, int n_in,
                              void* d_out, int out_size)
{
    const float* x      = (const float*)d_in[0];
    const float* w_qkv  = (const float*)d_in[1];
    const float* b_qkv  = (const float*)d_in[2];
    const float* w_proj = (const float*)d_in[3];
    const float* b_proj = (const float*)d_in[4];
    float* out = (float*)d_out;

    // 1) QKV GEMM + bias -> Q (scaled), K, V^T scratch
    mm_kernel<128, 0><<<dim3(18, 32, 1), 256>>>(x, w_qkv, b_qkv, nullptr);
    // 2) S = Q @ K^T (batched over 24 heads)
    mm_kernel<128, 1><<<dim3(16, 16, 24), 256>>>(nullptr, nullptr, nullptr, nullptr);
    // 3) softmax rows of S in place
    softmax_kernel<<<BH * SEQ, 256>>>();
    // 4) O = P @ V  -> g_AO
    mm_kernel<64, 2><<<dim3(1, 16, 24), 256>>>(nullptr, nullptr, nullptr, nullptr);
    // 5) proj + bias -> out
    mm_kernel<128, 3><<<dim3(6, 32, 1), 256>>>(nullptr, w_proj, b_proj, out);
}

// round 4
// speedup vs baseline: 4.2518x; 1.3569x over previous
#include <cuda_runtime.h>
#include <cstdint>

#define SEQ   2048
#define EMB   768
#define NHEAD 12
#define HDIM  64
#define BH    24          // batch * heads
#define MTOT  4096        // batch * seq

// ---------------- scratch (allocation-free), all stored tf32-rounded ----------------
__device__ float g_Qs[(size_t)BH*SEQ*HDIM];   // scaled Q  [bh, n, d]
__device__ float g_Kc[(size_t)BH*SEQ*HDIM];   // K         [bh, n, d]
__device__ float g_V [(size_t)BH*SEQ*HDIM];   // V         [bh, n, d]
__device__ float g_AO[(size_t)MTOT*EMB];      // attention out [b, n, c]

// ---------------- helpers ----------------
__device__ __forceinline__ uint32_t f2tf(float x){
    uint32_t r; asm("cvt.rna.tf32.f32 %0, %1;" : "=r"(r) : "f"(x)); return r;
}
__device__ __forceinline__ void cp16(uint32_t dst, const void* src){
    asm volatile("cp.async.cg.shared.global [%0], [%1], 16;" :: "r"(dst), "l"(src));
}
__device__ __forceinline__ void cp_commit(){
    asm volatile("cp.async.commit_group;" ::: "memory");
}
template<int N>
__device__ __forceinline__ void cp_wait(){
    asm volatile("cp.async.wait_group %0;" :: "n"(N) : "memory");
}
__device__ __forceinline__ void mma_tf32(float* c, const uint32_t* a, const uint32_t* b){
    asm volatile(
        "mma.sync.aligned.m16n8k8.row.col.f32.tf32.tf32.f32 "
        "{%0,%1,%2,%3}, {%4,%5,%6,%7}, {%8,%9}, {%0,%1,%2,%3};"
        : "+f"(c[0]), "+f"(c[1]), "+f"(c[2]), "+f"(c[3])
        : "r"(a[0]), "r"(a[1]), "r"(a[2]), "r"(a[3]), "r"(b[0]), "r"(b[1]));
}

// ----------------------------------------------------------------------------
// tf32 mma.sync GEMM: D[128, 128] tile = A[M,K] @ B[N,K]^T + bias
//   MODE 0: QKV (A=x, B=w_qkv)     -> scatter tf32-rounded to g_Qs(x0.125)/g_Kc/g_V
//   MODE 3: proj (A=g_AO, B=w_proj)-> Cout + bias
// ----------------------------------------------------------------------------
template<int MODE>
__global__ void __launch_bounds__(256) mm_kernel(
    const float* __restrict__ Ain, const float* __restrict__ Bin,
    const float* __restrict__ bias, float* __restrict__ Cout)
{
    constexpr int BN = 128, BK = 16, LDS = 20, NT = BN / 16;

    __shared__ float As[2][128 * LDS];
    __shared__ float Bs[2][BN  * LDS];

    const int tid  = threadIdx.x;
    const int wid  = tid >> 5, lane = tid & 31;
    const int lq   = lane >> 2, lr = lane & 3;
    const int mOff = (wid & 3) * 32;
    const int nOff = (wid >> 2) * (BN / 2);
    const int row0 = blockIdx.y * 128, col0 = blockIdx.x * BN;

    const float* Ap = (MODE == 0) ? Ain : g_AO;
    const float* Bp = Bin;
    const int K = EMB;

    const uint32_t sA = (uint32_t)__cvta_generic_to_shared(&As[0][0]);
    const uint32_t sB = (uint32_t)__cvta_generic_to_shared(&Bs[0][0]);
    constexpr uint32_t ABYT = 128 * LDS * 4;
    constexpr uint32_t BBYT = BN  * LDS * 4;

    auto load_tile = [&](int kt, int buf){
        const float* ag = Ap + (size_t)row0 * K + kt * BK;
        const uint32_t da = sA + buf * ABYT;
        #pragma unroll
        for (int i = 0; i < 2; i++){
            int ch = tid + i * 256, r = ch >> 2, c4 = ch & 3;
            cp16(da + (uint32_t)(r * LDS + c4 * 4) * 4, ag + (size_t)r * K + c4 * 4);
        }
        const float* bg = Bp + (size_t)col0 * K + kt * BK;
        const uint32_t db = sB + buf * BBYT;
        #pragma unroll
        for (int i = 0; i < 2; i++){
            int ch = tid + i * 256, r = ch >> 2, c4 = ch & 3;
            cp16(db + (uint32_t)(r * LDS + c4 * 4) * 4, bg + (size_t)r * K + c4 * 4);
        }
    };

    float acc[2][NT][4];
    #pragma unroll
    for (int mt = 0; mt < 2; mt++)
        #pragma unroll
        for (int nt = 0; nt < NT; nt++)
            #pragma unroll
            for (int j = 0; j < 4; j++) acc[mt][nt][j] = 0.f;

    load_tile(0, 0);
    cp_commit();

    const int KT = K / BK;
    for (int kt = 0; kt < KT; kt++){
        if (kt + 1 < KT){ load_tile(kt + 1, (kt + 1) & 1); cp_commit(); cp_wait<1>(); }
        else            { cp_wait<0>(); }
        __syncthreads();

        const float* a_s = As[kt & 1];
        const float* b_s = Bs[kt & 1];
        #pragma unroll
        for (int s = 0; s < 2; s++){
            const int k0 = s * 8;
            uint32_t af[2][4];
            #pragma unroll
            for (int mt = 0; mt < 2; mt++){
                const int r = mOff + mt * 16 + lq;
                af[mt][0] = f2tf(a_s[(r    ) * LDS + k0 + lr    ]);
                af[mt][1] = f2tf(a_s[(r + 8) * LDS + k0 + lr    ]);
                af[mt][2] = f2tf(a_s[(r    ) * LDS + k0 + lr + 4]);
                af[mt][3] = f2tf(a_s[(r + 8) * LDS + k0 + lr + 4]);
            }
            uint32_t bf[NT][2];
            #pragma unroll
            for (int nt = 0; nt < NT; nt++){
                const int c = nOff + nt * 8 + lq;
                bf[nt][0] = f2tf(b_s[c * LDS + k0 + lr    ]);
                bf[nt][1] = f2tf(b_s[c * LDS + k0 + lr + 4]);
            }
            #pragma unroll
            for (int mt = 0; mt < 2; mt++)
                #pragma unroll
                for (int nt = 0; nt < NT; nt++)
                    mma_tf32(acc[mt][nt], af[mt], bf[nt]);
        }
        __syncthreads();
    }

    // ---------------- epilogue ----------------
    #pragma unroll
    for (int mt = 0; mt < 2; mt++){
        const int r1 = row0 + mOff + mt * 16 + lq;
        #pragma unroll
        for (int nt = 0; nt < NT; nt++){
            const int col = col0 + nOff + nt * 8 + lr * 2;
            #pragma unroll
            for (int half = 0; half < 2; half++){
                const int r = r1 + half * 8;
                const float v0 = acc[mt][nt][half * 2], v1 = acc[mt][nt][half * 2 + 1];
                if (MODE == 0){
                    const int part = col / EMB, cc = col - part * EMB;
                    const int h = cc >> 6, d = cc & 63;
                    const int bidx = r >> 11, n = r & (SEQ - 1);
                    const float sc = (part == 0) ? 0.125f : 1.0f;
                    float* dst = (part == 0 ? g_Qs : (part == 1 ? g_Kc : g_V))
                               + (((size_t)(bidx * NHEAD + h) * SEQ + n) * HDIM + d);
                    float2 w;
                    w.x = __uint_as_float(f2tf((v0 + bias[col    ]) * sc));
                    w.y = __uint_as_float(f2tf((v1 + bias[col + 1]) * sc));
                    *(float2*)dst = w;
                } else {
                    *(float2*)(Cout + (size_t)r * EMB + col)
                        = make_float2(v0 + bias[col], v1 + bias[col + 1]);
                }
            }
        }
    }
}

// ----------------------------------------------------------------------------
// Fused flash attention: g_AO[b,n,c] = softmax(Qs @ K^T) @ V  per head.
// Block = 128 query rows x 1 head; 8 warps x 16 rows; 64-key tiles,
// cp.async double-buffered. P routed through per-warp smem slice.
// All inputs pre-rounded to tf32; zero CVT in the hot loop.
// ----------------------------------------------------------------------------
__global__ void __launch_bounds__(256) attn_kernel()
{
    constexpr int TILE = 64, LDP = 72, NKT = SEQ / TILE;
    extern __shared__ float sm[];
    float* Ks = sm;                       // [2][64*72]
    float* Vs = sm + 2 * TILE * LDP;      // [2][64*72]
    float* Ps = sm + 4 * TILE * LDP;      // [128*72]  (Q staging, then P)

    const int tid  = threadIdx.x;
    const int wid  = tid >> 5, lane = tid & 31;
    const int lq   = lane >> 2, lr = lane & 3;
    const int z    = blockIdx.y;                 // head index (bh)
    const int row0 = blockIdx.x * 128;
    const size_t base = (size_t)z * SEQ * HDIM;

    // ---- stage Q into Ps, extract persistent fragments ----
    {
        const float* qg = g_Qs + base + (size_t)row0 * HDIM;
        #pragma unroll
        for (int i = 0; i < 8; i++){
            int ch = tid + i * 256, r = ch >> 4, c4 = ch & 15;
            *(float4*)&Ps[r * LDP + c4 * 4] = *(const float4*)(qg + r * HDIM + c4 * 4);
        }
    }
    __syncthreads();
    uint32_t qf[8][4];
    {
        const int r = wid * 16 + lq;
        #pragma unroll
        for (int ks = 0; ks < 8; ks++){
            qf[ks][0] = __float_as_uint(Ps[(r    ) * LDP + ks * 8 + lr    ]);
            qf[ks][1] = __float_as_uint(Ps[(r + 8) * LDP + ks * 8 + lr    ]);
            qf[ks][2] = __float_as_uint(Ps[(r    ) * LDP + ks * 8 + lr + 4]);
            qf[ks][3] = __float_as_uint(Ps[(r + 8) * LDP + ks * 8 + lr + 4]);
        }
    }

    float o[8][4];
    #pragma unroll
    for (int nt = 0; nt < 8; nt++)
        #pragma unroll
        for (int j = 0; j < 4; j++) o[nt][j] = 0.f;
    float m_lo = -1e30f, m_hi = -1e30f, l_lo = 0.f, l_hi = 0.f;

    auto load_kv = [&](int kt, int buf){
        const float* kg = g_Kc + base + (size_t)(kt * TILE) * HDIM;
        const float* vg = g_V  + base + (size_t)(kt * TILE) * HDIM;
        uint32_t kd = (uint32_t)__cvta_generic_to_shared(Ks + buf * TILE * LDP);
        uint32_t vd = (uint32_t)__cvta_generic_to_shared(Vs + buf * TILE * LDP);
        #pragma unroll
        for (int i = 0; i < 4; i++){              // 64x64 floats = 1024 float4
            int ch = tid + i * 256, r = ch >> 4, c4 = ch & 15;
            uint32_t off = (uint32_t)(r * LDP + c4 * 4) * 4;
            cp16(kd + off, kg + r * HDIM + c4 * 4);
            cp16(vd + off, vg + r * HDIM + c4 * 4);
        }
    };

    load_kv(0, 0);
    cp_commit();

    for (int kt = 0; kt < NKT; kt++){
        const int buf = kt & 1;
        cp_wait<0>();
        __syncthreads();
        if (kt + 1 < NKT){ load_kv(kt + 1, buf ^ 1); cp_commit(); }

        const float* ks_ = Ks + buf * TILE * LDP;
        const float* vs_ = Vs + buf * TILE * LDP;

        // ---- S = Q @ K^T (16 x 64 per warp) ----
        float s[8][4];
        #pragma unroll
        for (int nt = 0; nt < 8; nt++)
            #pragma unroll
            for (int j = 0; j < 4; j++) s[nt][j] = 0.f;
        #pragma unroll
        for (int ks = 0; ks < 8; ks++){
            uint32_t bf[8][2];
            #pragma unroll
            for (int nt = 0; nt < 8; nt++){
                bf[nt][0] = __float_as_uint(ks_[(nt * 8 + lq) * LDP + ks * 8 + lr    ]);
                bf[nt][1] = __float_as_uint(ks_[(nt * 8 + lq) * LDP + ks * 8 + lr + 4]);
            }
            #pragma unroll
            for (int nt = 0; nt < 8; nt++)
                mma_tf32(s[nt], qf[ks], bf[nt]);
        }

        // ---- online softmax (rows lq and lq+8 of this warp's 16) ----
        float mx_lo = -1e30f, mx_hi = -1e30f;
        #pragma unroll
        for (int nt = 0; nt < 8; nt++){
            mx_lo = fmaxf(mx_lo, fmaxf(s[nt][0], s[nt][1]));
            mx_hi = fmaxf(mx_hi, fmaxf(s[nt][2], s[nt][3]));
        }
        mx_lo = fmaxf(mx_lo, __shfl_xor_sync(~0u, mx_lo, 1));
        mx_lo = fmaxf(mx_lo, __shfl_xor_sync(~0u, mx_lo, 2));
        mx_hi = fmaxf(mx_hi, __shfl_xor_sync(~0u, mx_hi, 1));
        mx_hi = fmaxf(mx_hi, __shfl_xor_sync(~0u, mx_hi, 2));
        const float mn_lo = fmaxf(m_lo, mx_lo), mn_hi = fmaxf(m_hi, mx_hi);
        const float c_lo = __expf(m_lo - mn_lo), c_hi = __expf(m_hi - mn_hi);
        float sum_lo = 0.f, sum_hi = 0.f;
        #pragma unroll
        for (int nt = 0; nt < 8; nt++){
            s[nt][0] = __expf(s[nt][0] - mn_lo);
            s[nt][1] = __expf(s[nt][1] - mn_lo);
            s[nt][2] = __expf(s[nt][2] - mn_hi);
            s[nt][3] = __expf(s[nt][3] - mn_hi);
            sum_lo += s[nt][0] + s[nt][1];
            sum_hi += s[nt][2] + s[nt][3];
        }
        sum_lo += __shfl_xor_sync(~0u, sum_lo, 1);
        sum_lo += __shfl_xor_sync(~0u, sum_lo, 2);
        sum_hi += __shfl_xor_sync(~0u, sum_hi, 1);
        sum_hi += __shfl_xor_sync(~0u, sum_hi, 2);
        l_lo = l_lo * c_lo + sum_lo;
        l_hi = l_hi * c_hi + sum_hi;
        #pragma unroll
        for (int nt = 0; nt < 8; nt++){
            o[nt][0] *= c_lo; o[nt][1] *= c_lo;
            o[nt][2] *= c_hi; o[nt][3] *= c_hi;
        }
        m_lo = mn_lo; m_hi = mn_hi;

        // ---- write P (tf32-rounded) to this warp's smem slice ----
        const int pr = wid * 16 + lq;
        #pragma unroll
        for (int nt = 0; nt < 8; nt++){
            float2 w0, w1;
            w0.x = __uint_as_float(f2tf(s[nt][0]));
            w0.y = __uint_as_float(f2tf(s[nt][1]));
            w1.x = __uint_as_float(f2tf(s[nt][2]));
            w1.y = __uint_as_float(f2tf(s[nt][3]));
            *(float2*)&Ps[(pr    ) * LDP + nt * 8 + lr * 2] = w0;
            *(float2*)&Ps[(pr + 8) * LDP + nt * 8 + lr * 2] = w1;
        }
        __syncwarp();

        // ---- O += P @ V ----
        #pragma unroll
        for (int ks = 0; ks < 8; ks++){
            uint32_t af[4];
            af[0] = __float_as_uint(Ps[(pr    ) * LDP + ks * 8 + lr    ]);
            af[1] = __float_as_uint(Ps[(pr + 8) * LDP + ks * 8 + lr    ]);
            af[2] = __float_as_uint(Ps[(pr    ) * LDP + ks * 8 + lr + 4]);
            af[3] = __float_as_uint(Ps[(pr + 8) * LDP + ks * 8 + lr + 4]);
            #pragma unroll
            for (int nt = 0; nt < 8; nt++){
                uint32_t bf2[2];
                bf2[0] = __float_as_uint(vs_[(ks * 8 + lr    ) * LDP + nt * 8 + lq]);
                bf2[1] = __float_as_uint(vs_[(ks * 8 + lr + 4) * LDP + nt * 8 + lq]);
                mma_tf32(o[nt], af, bf2);
            }
        }
        __syncwarp();
    }

    // ---- epilogue: O / l -> g_AO[b, n, h*64 + d] ----
    const float inv_lo = 1.f / l_lo, inv_hi = 1.f / l_hi;
    const int bidx = z / NHEAD, h = z - bidx * NHEAD;
    const int r = row0 + wid * 16 + lq;
    float* ob = g_AO + ((size_t)(bidx * SEQ + r)) * EMB + h * HDIM;
    #pragma unroll
    for (int nt = 0; nt < 8; nt++){
        const int col = nt * 8 + lr * 2;
        *(float2*)(ob + col)             = make_float2(o[nt][0] * inv_lo, o[nt][1] * inv_lo);
        *(float2*)(ob + 8 * EMB + col)   = make_float2(o[nt][2] * inv_hi, o[nt][3] * inv_hi);
    }
}

// ----------------------------------------------------------------------------
extern "C" void kernel_launch(void* const* d_in, const int* in_sizes, int n_in,
                              void* d_out, int out_size)
{
    const float* x      = (const float*)d_in[0];
    const float* w_qkv  = (const float*)d_in[1];
    const float* b_qkv  = (const float*)d_in[2];
    const float* w_proj = (const float*)d_in[3];
    const float* b_proj = (const float*)d_in[4];
    float* out = (float*)d_out;

    constexpr int ASMEM = (4 * 64 * 72 + 128 * 72) * 4;   // 110592 B
    cudaFuncSetAttribute(attn_kernel, cudaFuncAttributeMaxDynamicSharedMemorySize, ASMEM);

    // 1) QKV GEMM + bias -> tf32-rounded Q(scaled)/K/V scratch
    mm_kernel<0><<<dim3(18, 32), 256>>>(x, w_qkv, b_qkv, nullptr);
    // 2) fused flash attention -> g_AO
    attn_kernel<<<dim3(SEQ / 128, BH), 256, ASMEM>>>();
    // 3) proj + bias -> out
    mm_kernel<3><<<dim3(6, 32), 256>>>(nullptr, w_proj, b_proj, out);
}